// round 16
// baseline (speedup 1.0000x reference)
#include <cuda_runtime.h>
#include <cuda_bf16.h>
#include <math.h>
#include <stdint.h>

// ---------------- constants ----------------
#define S_   16
#define N_   256
#define D_   128
#define RR   49
#define K1   2401            // 49*49
#define VSTR 2416            // padded vol row stride (mult of 16)
#define ROWS_T 12288         // 3 levels * 16 * 256

// fmapT offsets
#define FT1_OFF 6291456      // 16*48*64*128
#define FT2_OFF 7864320      // + 16*24*32*128

// ---------------- scratch (static device memory; no allocs) ----------------
__device__ float g_fmapT[8257536];           // all 3 transposed fmaps
__device__ float g_vol[ROWS_T * VSTR];       // 12288 x 2416
__device__ float g_h[ROWS_T * 384];
__device__ float g_emb[ROWS_T * 256];
__device__ float g_w1r[K1 * 384];            // tf32-rounded W1
__device__ float g_w2r[384 * 256];           // tf32-rounded W2

// ---------------- helpers ----------------
__device__ __forceinline__ uint32_t f2tf32(float f)
{
    uint32_t r;
    asm("cvt.rna.tf32.f32 %0, %1;" : "=r"(r) : "f"(f));
    return r;
}

__device__ __forceinline__ float tf32r(float f) { return __uint_as_float(f2tf32(f)); }

__device__ __forceinline__ void mma_tf32(float* c, const uint32_t* a, const uint32_t* b)
{
    asm volatile(
        "mma.sync.aligned.m16n8k8.row.col.f32.tf32.tf32.f32 "
        "{%0,%1,%2,%3}, {%4,%5,%6,%7}, {%8,%9}, {%0,%1,%2,%3};"
        : "+f"(c[0]), "+f"(c[1]), "+f"(c[2]), "+f"(c[3])
        : "r"(a[0]), "r"(a[1]), "r"(a[2]), "r"(a[3]), "r"(b[0]), "r"(b[1]));
}

__device__ __forceinline__ void cpa16(uint32_t dst, const void* src, bool pred)
{
    asm volatile("cp.async.ca.shared.global [%0], [%1], 16, %2;"
                 :: "r"(dst), "l"(src), "r"(pred ? 16 : 0) : "memory");
}
__device__ __forceinline__ void cpa_commit() { asm volatile("cp.async.commit_group;" ::: "memory"); }
__device__ __forceinline__ void cpa_wait0()  { asm volatile("cp.async.wait_group 0;" ::: "memory"); }
__device__ __forceinline__ void cpa_wait1()  { asm volatile("cp.async.wait_group 1;" ::: "memory"); }
__device__ __forceinline__ void cpa_wait2()  { asm volatile("cp.async.wait_group 2;" ::: "memory"); }

// ---------------- fused transpose [S,D,H,W] -> [S,H*W,D], all 3 levels -------
__global__ void transpose_all_kernel(const float* __restrict__ fm0,
                                     const float* __restrict__ fm1,
                                     const float* __restrict__ fm2,
                                     float* __restrict__ dstBase)
{
    __shared__ float tile[32][33];
    int bx = blockIdx.x;
    const float* src;
    float* dst;
    int HW;
    if (bx < 96)       { src = fm0; dst = dstBase;           HW = 3072; }
    else if (bx < 120) { src = fm1; dst = dstBase + FT1_OFF; HW = 768;  bx -= 96; }
    else               { src = fm2; dst = dstBase + FT2_OFF; HW = 192;  bx -= 120; }

    int s   = blockIdx.z;
    int hw0 = bx * 32;
    int d0  = blockIdx.y * 32;
    int tx  = threadIdx.x;
    for (int i = threadIdx.y; i < 32; i += 8)
        tile[i][tx] = src[(size_t)(s * D_ + d0 + i) * HW + hw0 + tx];
    __syncthreads();
    for (int i = threadIdx.y; i < 32; i += 8)
        dst[(size_t)(s * HW + hw0 + i) * D_ + d0 + tx] = tile[tx][i];
}

// ---------------- round both weight tensors to tf32-representable fp32 -------
__global__ void round2_kernel(const float* __restrict__ W1s, float* __restrict__ w1d, int n1,
                              const float* __restrict__ W2s, float* __restrict__ w2d, int n2)
{
    int i = blockIdx.x * 256 + threadIdx.x;
    if (i < n1) w1d[i] = tf32r(W1s[i]);
    else {
        int j = i - n1;
        if (j < n2) w2d[j] = tf32r(W2s[j]);
    }
}

// ---------------- zero the vol pad columns (K1..VSTR-1 of every row) --------
__global__ void padzero_kernel(float* __restrict__ vol)
{
    int i = blockIdx.x * 256 + threadIdx.x;
    const int NPAD = VSTR - K1;                  // 15
    if (i < ROWS_T * NPAD) {
        const int r = i / NPAD, c = i - r * NPAD;
        vol[(size_t)r * VSTR + K1 + c] = 0.f;
    }
}

// ---------------- vol kernel: per-(s,n,lev) block, cp.async gather ----------
// As raw [64][132], Bs raw [56][132] (rows 49..55 unread garbage);
// tf32 rounding happens in the fragment loads. C overlays smem after mma.
#define VAW 132
#define VA_SZ (64 * VAW)    // 8448 floats
#define VB_SZ (56 * VAW)    // 7392 floats
#define VOL_SMEM ((VA_SZ + VB_SZ) * 4)   // 63360 B

__global__ __launch_bounds__(256)
void vol_kernel(const float* __restrict__ fmTbase,
                const float* __restrict__ tf0,
                const float* __restrict__ tf1,
                const float* __restrict__ tf2,
                const float* __restrict__ coords, float* __restrict__ vol)
{
    extern __shared__ float smv[];
    float* As = smv;            // [64][132] raw texels
    float* Bs = smv + VA_SZ;    // [56][132] raw tf

    const int n = blockIdx.x, s = blockIdx.y, lev = blockIdx.z;
    const int tid = threadIdx.x, lane = tid & 31, wp = tid >> 5;

    int H, W, off;
    float invscale;
    const float* tfs;
    if (lev == 0)      { H = 48; W = 64; off = 0;       invscale = 1.0f;  tfs = tf0; }
    else if (lev == 1) { H = 24; W = 32; off = FT1_OFF; invscale = 0.5f;  tfs = tf1; }
    else               { H = 12; W = 16; off = FT2_OFF; invscale = 0.25f; tfs = tf2; }

    const int sn = s * N_ + n;
    const float cx = coords[sn * 2 + 0] * invscale;
    const float cy = coords[sn * 2 + 1] * invscale;
    const float fxx = floorf(cx), fyy = floorf(cy);
    const int   ix0 = (int)fxx,   iy0 = (int)fyy;
    const float fx = cx - fxx,    fy = cy - fyy;
    const float w00 = (1.f - fx) * (1.f - fy);
    const float w01 = fx * (1.f - fy);
    const float w10 = (1.f - fx) * fy;
    const float w11 = fx * fy;
    const float* base = fmTbase + off + (size_t)s * H * W * D_;

    const uint32_t smbase = (uint32_t)__cvta_generic_to_shared(smv);

    // ---- cp.async gather: A = 8x8 texel patch (zfill OOB), B = tf rows ----
    {
        const int arow = tid >> 2;               // 0..63
        const int ac0  = (tid & 3) * 8;          // first of 8 float4 chunks
        const int aty = arow >> 3, atx = arow & 7;
        const int yy = iy0 + aty - 3, xx = ix0 + atx - 3;
        const bool valid = (yy >= 0) && (yy < H) && (xx >= 0) && (xx < W);
        const float* gp = base + ((long)yy * W + xx) * D_ + ac0 * 4;
        const uint32_t sa = smbase + (uint32_t)(arow * VAW) * 4 + (uint32_t)ac0 * 16;
        #pragma unroll
        for (int q = 0; q < 8; q++)
            cpa16(sa + q * 16, gp + q * 4, valid);
    }
    for (int ij = wp; ij < RR; ij += 8)
        cpa16(smbase + (uint32_t)(VA_SZ + ij * VAW) * 4 + (uint32_t)lane * 16,
              tfs + ((long)ij * N_ + n) * D_ + lane * 4, true);
    cpa_commit();
    cpa_wait0();
    __syncthreads();

    // mma: warp -> m tile (warp&3)*16, n half (warp>>2); C = texels . tf
    const int wm  = (wp & 3) * 16;
    const int nh  = wp >> 2;
    const int nt0 = nh ? 4 : 0;
    const int ntN = nh ? 3 : 4;
    const int t = lane & 3, g = lane >> 2;

    float acc[4][4];
    #pragma unroll
    for (int i = 0; i < 4; i++)
        #pragma unroll
        for (int q = 0; q < 4; q++) acc[i][q] = 0.f;

    #pragma unroll
    for (int kb = 0; kb < 16; kb++) {
        const int kc = kb * 8 + t;
        uint32_t a[4];
        const int ra = (wm + g) * VAW + kc;
        const int rb = (wm + g + 8) * VAW + kc;
        a[0] = f2tf32(As[ra]);     a[1] = f2tf32(As[rb]);
        a[2] = f2tf32(As[ra + 4]); a[3] = f2tf32(As[rb + 4]);
        #pragma unroll
        for (int ni = 0; ni < 4; ni++) {
            if (ni >= ntN) break;
            const int nb = ((nt0 + ni) * 8 + g) * VAW + kc;
            uint32_t b[2];
            b[0] = f2tf32(Bs[nb]); b[1] = f2tf32(Bs[nb + 4]);
            mma_tf32(acc[ni], a, b);
        }
    }

    // store C to smem (reuse region), then bilinear-combine in output space
    __syncthreads();
    float* Cs = smv;    // [64][56]
    #pragma unroll
    for (int ni = 0; ni < 4; ni++) {
        if (ni >= ntN) break;
        const int col0 = (nt0 + ni) * 8 + 2 * t;
        *(float2*)&Cs[(wm + g) * 56 + col0]     = make_float2(acc[ni][0], acc[ni][1]);
        *(float2*)&Cs[(wm + g + 8) * 56 + col0] = make_float2(acc[ni][2], acc[ni][3]);
    }
    __syncthreads();

    float* vrow = vol + (size_t)(lev * 4096 + sn) * VSTR;
    for (int idx = tid; idx < K1; idx += 256) {
        const int hw = idx / 49, ij = idx - hw * 49;
        const int h = hw / 7,  w = hw - h * 7;
        const int m00 = h * 8 + w;
        const float v = w00 * Cs[m00 * 56 + ij]
                      + w01 * Cs[(m00 + 1) * 56 + ij]
                      + w10 * Cs[(m00 + 8) * 56 + ij]
                      + w11 * Cs[(m00 + 9) * 56 + ij];
        vrow[idx] = tf32r(v);
    }
}

// ---------------- 3-stage tf32 GEMM, 128x128 tile, 4 warps of 64x64,
// register-double-buffered fragments ------------------------------------
__device__ __forceinline__ float gelu_exact(float v)
{
    return 0.5f * v * (1.f + erff(v * 0.7071067811865475f));
}

#define AST 20   // A smem word stride per m row (16 k + pad)
#define BST 136  // B smem word stride per k row (128 n + pad)
#define STG_A (128 * AST)   // 2560 words
#define STG_B (16 * BST)    // 2176 words
#define GEMM_SMEM (3 * (STG_A + STG_B) * 4)   // 56832 B

template <bool GELU, bool ROUND_OUT>
__global__ __launch_bounds__(128, 2)
void tf32_gemm_pipe(const float* __restrict__ A, int lda,
                    const float* __restrict__ B, int ldb,
                    const float* __restrict__ bias,
                    float* __restrict__ C, int ldc,
                    int K, int Kvalid)
{
    extern __shared__ float smg[];
    float* AsBase = smg;                    // 3 x STG_A
    float* BsBase = smg + 3 * STG_A;        // 3 x STG_B

    const int tid  = threadIdx.x;
    const int lane = tid & 31;
    const int warp = tid >> 5;              // 0..3
    const int m0 = blockIdx.y * 128, n0 = blockIdx.x * 128;
    const int wm = (warp >> 1) * 64, wn = (warp & 1) * 64;
    const int t = lane & 3, g = lane >> 2;

    // staging assignments (128 threads)
    const int am  = tid;
    const int bk0 = tid >> 5;               // 0..3
    const int bnc = (tid & 31) * 4;

    uint32_t sA[3], sB[3];
    {
        uint32_t a = (uint32_t)__cvta_generic_to_shared(AsBase);
        uint32_t b = (uint32_t)__cvta_generic_to_shared(BsBase);
        #pragma unroll
        for (int st = 0; st < 3; st++) {
            sA[st] = a + (st * STG_A + am * AST) * 4;
            sB[st] = b + (st * STG_B + bk0 * BST + bnc) * 4;
        }
    }
    const float* gA = A + (size_t)(m0 + am) * lda;
    const float* gB = B + (size_t)bk0 * ldb + n0 + bnc;

    const int NIT = K / 16;

    auto prefetch = [&](int it, int st) {
        const int k0 = it * 16;
        #pragma unroll
        for (int q = 0; q < 4; q++)
            cpa16(sA[st] + q * 16, gA + k0 + q * 4, true);
        #pragma unroll
        for (int q = 0; q < 4; q++)
            cpa16(sB[st] + q * 4 * BST * 4,
                  gB + (size_t)(k0 + q * 4) * ldb,
                  k0 + bk0 + q * 4 < Kvalid);
        cpa_commit();
    };

    auto ldfrag = [&](const float* Ab, const float* Bb, int kb,
                      uint32_t af[4][4], uint32_t bf[8][2]) {
        #pragma unroll
        for (int mi = 0; mi < 4; mi++) {
            const int r = (wm + mi * 16 + g) * AST + kb + t;
            af[mi][0] = __float_as_uint(Ab[r]);
            af[mi][1] = __float_as_uint(Ab[r + 8 * AST]);
            af[mi][2] = __float_as_uint(Ab[r + 4]);
            af[mi][3] = __float_as_uint(Ab[r + 8 * AST + 4]);
        }
        #pragma unroll
        for (int ni = 0; ni < 8; ni++) {
            const int cidx = (kb + t) * BST + wn + ni * 8 + g;
            bf[ni][0] = __float_as_uint(Bb[cidx]);
            bf[ni][1] = __float_as_uint(Bb[cidx + 4 * BST]);
        }
    };

    float acc[4][8][4];
    #pragma unroll
    for (int mi = 0; mi < 4; mi++)
        #pragma unroll
        for (int ni = 0; ni < 8; ni++)
            #pragma unroll
            for (int q = 0; q < 4; q++) acc[mi][ni][q] = 0.f;

    auto dommas = [&](uint32_t af[4][4], uint32_t bf[8][2]) {
        #pragma unroll
        for (int mi = 0; mi < 4; mi++)
            #pragma unroll
            for (int ni = 0; ni < 8; ni++)
                mma_tf32(acc[mi][ni], af[mi], bf[ni]);
    };

    prefetch(0, 0);
    if (1 < NIT) prefetch(1, 1);

    uint32_t afA[4][4], bfA[8][2], afB[4][4], bfB[8][2];
    bool first = true;

    for (int it = 0; it < NIT; it++) {
        const int st = it % 3;
        if (it + 2 < NIT) {
            prefetch(it + 2, (it + 2) % 3);
            cpa_wait1();
        } else {
            cpa_wait0();
        }
        __syncthreads();

        const float* Ab = AsBase + st * STG_A;
        const float* Bb = BsBase + st * STG_B;
        if (first) { ldfrag(Ab, Bb, 0, afA, bfA); first = false; }
        ldfrag(Ab, Bb, 8, afB, bfB);
        dommas(afA, bfA);
        if (it + 1 < NIT) {
            const int stn = (it + 1) % 3;
            ldfrag(AsBase + stn * STG_A, BsBase + stn * STG_B, 0, afA, bfA);
        }
        dommas(afB, bfB);
        __syncthreads();
    }

    // epilogue: bias (+gelu) (+tf32 round), write C
    #pragma unroll
    for (int mi = 0; mi < 4; mi++) {
        const int r0 = m0 + wm + mi * 16 + g;
        #pragma unroll
        for (int ni = 0; ni < 8; ni++) {
            const int c0 = n0 + wn + ni * 8 + 2 * t;
            const float bb0 = bias[c0], bb1 = bias[c0 + 1];
            float v0 = acc[mi][ni][0] + bb0;
            float v1 = acc[mi][ni][1] + bb1;
            float v2 = acc[mi][ni][2] + bb0;
            float v3 = acc[mi][ni][3] + bb1;
            if (GELU) {
                v0 = gelu_exact(v0); v1 = gelu_exact(v1);
                v2 = gelu_exact(v2); v3 = gelu_exact(v3);
            }
            if (ROUND_OUT) {
                v0 = tf32r(v0); v1 = tf32r(v1);
                v2 = tf32r(v2); v3 = tf32r(v3);
            }
            *(float2*)(C + (size_t)r0 * ldc + c0)       = make_float2(v0, v1);
            *(float2*)(C + (size_t)(r0 + 8) * ldc + c0) = make_float2(v2, v3);
        }
    }
}

// ---------------- final assembly: concat + posenc + time embedding ----------------
__global__ void assemble_kernel(const float* __restrict__ emb,
                                const float* __restrict__ coords,
                                const float* __restrict__ vis,
                                const float* __restrict__ conf,
                                float* __restrict__ out)
{
    const int n = blockIdx.x, s = blockIdx.y;
    const int sn = s * N_ + n;

    float rfx = 0.f, rfy = 0.f, rbx = 0.f, rby = 0.f;
    const float cx = coords[sn * 2], cy = coords[sn * 2 + 1];
    if (s < S_ - 1) {
        rfx = cx - coords[((s + 1) * N_ + n) * 2];
        rfy = cy - coords[((s + 1) * N_ + n) * 2 + 1];
    }
    if (s > 0) {
        rbx = cx - coords[((s - 1) * N_ + n) * 2];
        rby = cy - coords[((s - 1) * N_ + n) * 2 + 1];
    }
    float p4[4];
    p4[0] = rfx / 64.f;
    p4[1] = rfy / 48.f;
    p4[2] = rbx / 64.f;
    p4[3] = rby / 48.f;

    float* orow = out + (size_t)(n * S_ + s) * 854;
    for (int f = threadIdx.x; f < 854; f += 256) {
        float v;
        if (f == 0)      v = vis[sn];
        else if (f == 1) v = conf[sn];
        else if (f < 770) {
            const int lev = (f - 2) >> 8;
            const int c   = (f - 2) & 255;
            v = emb[((size_t)(lev * 4096 + sn)) * 256 + c];
        } else {
            const int j = f - 770;
            if (j < 4) v = p4[j];
            else if (j < 44) {
                const int i = (j - 4) >> 2, q = (j - 4) & 3;
                v = sinf(exp2f((float)i) * p4[q]);
            } else {
                const int i = (j - 44) >> 2, q = (j - 44) & 3;
                v = sinf(exp2f((float)i) * p4[q] + 1.5707963267948966f);
            }
        }
        const int i2 = (f < 427) ? f : f - 427;
        const float omega = expf(-9.210340371976184f * (float)i2 / 427.0f);
        const float ang = (float)s * omega;
        v += (f < 427) ? sinf(ang) : cosf(ang);
        orow[f] = v;
    }
}

// ---------------- launch ----------------
extern "C" void kernel_launch(void* const* d_in, const int* in_sizes, int n_in,
                              void* d_out, int out_size)
{
    (void)in_sizes; (void)n_in; (void)out_size;
    const float* fm0    = (const float*)d_in[0];
    const float* fm1    = (const float*)d_in[1];
    const float* fm2    = (const float*)d_in[2];
    const float* coords = (const float*)d_in[3];
    const float* tf0    = (const float*)d_in[4];
    const float* tf1    = (const float*)d_in[5];
    const float* tf2    = (const float*)d_in[6];
    const float* vis    = (const float*)d_in[7];
    const float* conf   = (const float*)d_in[8];
    const float* W1     = (const float*)d_in[9];
    const float* b1     = (const float*)d_in[10];
    const float* W2     = (const float*)d_in[11];
    const float* W2b    = (const float*)d_in[12];
    float* out = (float*)d_out;

    float *fT, *vol, *hbuf, *ebuf, *w1r, *w2r;
    cudaGetSymbolAddress((void**)&fT,   g_fmapT);
    cudaGetSymbolAddress((void**)&vol,  g_vol);
    cudaGetSymbolAddress((void**)&hbuf, g_h);
    cudaGetSymbolAddress((void**)&ebuf, g_emb);
    cudaGetSymbolAddress((void**)&w1r,  g_w1r);
    cudaGetSymbolAddress((void**)&w2r,  g_w2r);

    cudaFuncSetAttribute(vol_kernel, cudaFuncAttributeMaxDynamicSharedMemorySize, VOL_SMEM);
    cudaFuncSetAttribute(tf32_gemm_pipe<true,  true >, cudaFuncAttributeMaxDynamicSharedMemorySize, GEMM_SMEM);
    cudaFuncSetAttribute(tf32_gemm_pipe<false, false>, cudaFuncAttributeMaxDynamicSharedMemorySize, GEMM_SMEM);

    // launch order puts vol at profiled slot #4
    transpose_all_kernel<<<dim3(126, 4, 16), dim3(32, 8)>>>(fm0, fm1, fm2, fT);

    const int NR = K1 * 384 + 384 * 256;
    round2_kernel<<<(NR + 255) / 256, 256>>>(W1, w1r, K1 * 384, W2, w2r, 384 * 256);

    const int NZ = ROWS_T * (VSTR - K1);
    padzero_kernel<<<(NZ + 255) / 256, 256>>>(vol);

    vol_kernel<<<dim3(N_, S_, 3), 256, VOL_SMEM>>>(fT, tf0, tf1, tf2, coords, vol);

    tf32_gemm_pipe<true,  true ><<<dim3(3, 96), 128, GEMM_SMEM>>>(vol,  VSTR, w1r, 384, b1,  hbuf, 384, VSTR, K1);
    tf32_gemm_pipe<false, false><<<dim3(2, 96), 128, GEMM_SMEM>>>(hbuf, 384,  w2r, 256, W2b, ebuf, 256, 384,  384);

    assemble_kernel<<<dim3(N_, S_), 256>>>(ebuf, coords, vis, conf, out);
}

// round 17
// speedup vs baseline: 1.3011x; 1.3011x over previous
#include <cuda_runtime.h>
#include <cuda_fp16.h>
#include <math.h>
#include <stdint.h>

// ---------------- constants ----------------
#define S_   16
#define N_   256
#define D_   128
#define RR   49
#define K1   2401            // 49*49
#define VSTRH 2432           // padded vol row stride in halves (76 * 32)
#define ROWS_T 12288         // 3 levels * 16 * 256

// fmapT offsets
#define FT1_OFF 6291456      // 16*48*64*128
#define FT2_OFF 7864320      // + 16*24*32*128

// ---------------- scratch (static device memory; no allocs) ----------------
__device__ float  g_fmapT[8257536];          // all 3 transposed fmaps
__device__ __half g_volh[ROWS_T * VSTRH];    // 12288 x 2432 fp16
__device__ float  g_h[ROWS_T * 384];
__device__ float  g_emb[ROWS_T * 256];
__device__ __half g_w1h[384 * VSTRH];        // W1^T fp16, [n][k]
__device__ float  g_w2r[384 * 256];          // tf32-rounded W2

// ---------------- helpers ----------------
__device__ __forceinline__ uint32_t f2tf32(float f)
{
    uint32_t r;
    asm("cvt.rna.tf32.f32 %0, %1;" : "=r"(r) : "f"(f));
    return r;
}
__device__ __forceinline__ float tf32r(float f) { return __uint_as_float(f2tf32(f)); }

__device__ __forceinline__ void mma_tf32(float* c, const uint32_t* a, const uint32_t* b)
{
    asm volatile(
        "mma.sync.aligned.m16n8k8.row.col.f32.tf32.tf32.f32 "
        "{%0,%1,%2,%3}, {%4,%5,%6,%7}, {%8,%9}, {%0,%1,%2,%3};"
        : "+f"(c[0]), "+f"(c[1]), "+f"(c[2]), "+f"(c[3])
        : "r"(a[0]), "r"(a[1]), "r"(a[2]), "r"(a[3]), "r"(b[0]), "r"(b[1]));
}

__device__ __forceinline__ void mma_f16(float* c, const uint32_t* a, const uint32_t* b)
{
    asm volatile(
        "mma.sync.aligned.m16n8k16.row.col.f32.f16.f16.f32 "
        "{%0,%1,%2,%3}, {%4,%5,%6,%7}, {%8,%9}, {%0,%1,%2,%3};"
        : "+f"(c[0]), "+f"(c[1]), "+f"(c[2]), "+f"(c[3])
        : "r"(a[0]), "r"(a[1]), "r"(a[2]), "r"(a[3]), "r"(b[0]), "r"(b[1]));
}

__device__ __forceinline__ void cpa16(uint32_t dst, const void* src, bool pred)
{
    asm volatile("cp.async.ca.shared.global [%0], [%1], 16, %2;"
                 :: "r"(dst), "l"(src), "r"(pred ? 16 : 0) : "memory");
}
__device__ __forceinline__ void cpa_commit() { asm volatile("cp.async.commit_group;" ::: "memory"); }
__device__ __forceinline__ void cpa_wait0()  { asm volatile("cp.async.wait_group 0;" ::: "memory"); }
__device__ __forceinline__ void cpa_wait1()  { asm volatile("cp.async.wait_group 1;" ::: "memory"); }
__device__ __forceinline__ void cpa_wait2()  { asm volatile("cp.async.wait_group 2;" ::: "memory"); }

__device__ __forceinline__ float gelu_exact(float v)
{
    return 0.5f * v * (1.f + erff(v * 0.7071067811865475f));
}

// ---------------- fused transpose [S,D,H,W] -> [S,H*W,D], all 3 levels -------
__global__ void transpose_all_kernel(const float* __restrict__ fm0,
                                     const float* __restrict__ fm1,
                                     const float* __restrict__ fm2,
                                     float* __restrict__ dstBase)
{
    __shared__ float tile[32][33];
    int bx = blockIdx.x;
    const float* src;
    float* dst;
    int HW;
    if (bx < 96)       { src = fm0; dst = dstBase;           HW = 3072; }
    else if (bx < 120) { src = fm1; dst = dstBase + FT1_OFF; HW = 768;  bx -= 96; }
    else               { src = fm2; dst = dstBase + FT2_OFF; HW = 192;  bx -= 120; }

    int s   = blockIdx.z;
    int hw0 = bx * 32;
    int d0  = blockIdx.y * 32;
    int tx  = threadIdx.x;
    for (int i = threadIdx.y; i < 32; i += 8)
        tile[i][tx] = src[(size_t)(s * D_ + d0 + i) * HW + hw0 + tx];
    __syncthreads();
    for (int i = threadIdx.y; i < 32; i += 8)
        dst[(size_t)(s * HW + hw0 + i) * D_ + d0 + tx] = tile[tx][i];
}

// ---------------- pack: W1 -> fp16 W1^T [n][k]; W2 -> tf32-rounded -----------
__global__ void pack_kernel(const float* __restrict__ W1s, __half* __restrict__ w1h,
                            const float* __restrict__ W2s, float* __restrict__ w2d)
{
    const int N1 = 384 * VSTRH;
    int i = blockIdx.x * 256 + threadIdx.x;
    if (i < N1) {
        const int n = i / VSTRH, k = i - n * VSTRH;
        w1h[i] = (k < K1) ? __float2half_rn(W1s[(size_t)k * 384 + n]) : __float2half_rn(0.f);
    } else {
        int j = i - N1;
        if (j < 384 * 256) w2d[j] = tf32r(W2s[j]);
    }
}

// ---------------- vol kernel: per-(s,n,lev) block (R14-proven path) ----------
#define VAW 132
#define VA_SZ (64 * VAW)    // 8448 floats
#define VB_SZ (56 * VAW)    // 7392 floats
#define VOL_SMEM ((VA_SZ + VB_SZ) * 4)   // 63360 B

__global__ __launch_bounds__(256)
void vol_kernel(const float* __restrict__ fmTbase,
                const float* __restrict__ tf0,
                const float* __restrict__ tf1,
                const float* __restrict__ tf2,
                const float* __restrict__ coords, __half* __restrict__ volh)
{
    extern __shared__ float smv[];
    float* As = smv;            // [64][132]
    float* Bs = smv + VA_SZ;    // [56][132]

    const int n = blockIdx.x, s = blockIdx.y, lev = blockIdx.z;
    const int tid = threadIdx.x, lane = tid & 31, wp = tid >> 5;

    int H, W, off;
    float invscale;
    const float* tfs;
    if (lev == 0)      { H = 48; W = 64; off = 0;       invscale = 1.0f;  tfs = tf0; }
    else if (lev == 1) { H = 24; W = 32; off = FT1_OFF; invscale = 0.5f;  tfs = tf1; }
    else               { H = 12; W = 16; off = FT2_OFF; invscale = 0.25f; tfs = tf2; }

    const int sn = s * N_ + n;
    const float cx = coords[sn * 2 + 0] * invscale;
    const float cy = coords[sn * 2 + 1] * invscale;
    const float fxx = floorf(cx), fyy = floorf(cy);
    const int   ix0 = (int)fxx,   iy0 = (int)fyy;
    const float fx = cx - fxx,    fy = cy - fyy;
    const float w00 = (1.f - fx) * (1.f - fy);
    const float w01 = fx * (1.f - fy);
    const float w10 = (1.f - fx) * fy;
    const float w11 = fx * fy;
    const float* base = fmTbase + off + (size_t)s * H * W * D_;

    // gather raw 8x8 texel patch: warp per texel row m; lane owns 4 channels
    #pragma unroll
    for (int m = wp; m < 64; m += 8) {
        const int ty = m >> 3, tx = m & 7;
        const int yy = iy0 + ty - 3, xx = ix0 + tx - 3;
        float4 t = make_float4(0.f, 0.f, 0.f, 0.f);
        if ((yy >= 0) && (yy < H) && (xx >= 0) && (xx < W))
            t = *(const float4*)(base + ((long)yy * W + xx) * D_ + 4 * lane);
        *(float4*)&As[m * VAW + 4 * lane] =
            make_float4(tf32r(t.x), tf32r(t.y), tf32r(t.z), tf32r(t.w));
    }
    // gather tf: warp per ij; lane owns 4 channels
    for (int ij = wp; ij < RR; ij += 8) {
        float4 t = *(const float4*)(tfs + ((long)ij * N_ + n) * D_ + 4 * lane);
        *(float4*)&Bs[ij * VAW + 4 * lane] =
            make_float4(tf32r(t.x), tf32r(t.y), tf32r(t.z), tf32r(t.w));
    }
    __syncthreads();

    __half* vrow = volh + (size_t)(lev * 4096 + sn) * VSTRH;
    if (tid < VSTRH - K1) vrow[K1 + tid] = __float2half_rn(0.f);

    // mma: warp -> m tile (warp&3)*16, n half (warp>>2); C = texels . tf
    const int wm  = (wp & 3) * 16;
    const int nh  = wp >> 2;
    const int nt0 = nh ? 4 : 0;
    const int ntN = nh ? 3 : 4;
    const int t = lane & 3, g = lane >> 2;
    const uint32_t* Au = (const uint32_t*)As;
    const uint32_t* Bu = (const uint32_t*)Bs;

    float acc[4][4];
    #pragma unroll
    for (int i = 0; i < 4; i++)
        #pragma unroll
        for (int q = 0; q < 4; q++) acc[i][q] = 0.f;

    #pragma unroll
    for (int kb = 0; kb < 16; kb++) {
        const int kc = kb * 8 + t;
        uint32_t a[4];
        const int ra = (wm + g) * VAW + kc;
        const int rb = (wm + g + 8) * VAW + kc;
        a[0] = Au[ra];     a[1] = Au[rb];
        a[2] = Au[ra + 4]; a[3] = Au[rb + 4];
        #pragma unroll
        for (int ni = 0; ni < 4; ni++) {
            if (ni >= ntN) break;
            const int nb = ((nt0 + ni) * 8 + g) * VAW + kc;
            uint32_t b[2];
            b[0] = Bu[nb]; b[1] = Bu[nb + 4];
            mma_tf32(acc[ni], a, b);
        }
    }

    // store C to smem (reuse region), then bilinear-combine in output space
    __syncthreads();
    float* Cs = smv;    // [64][56]
    #pragma unroll
    for (int ni = 0; ni < 4; ni++) {
        if (ni >= ntN) break;
        const int col0 = (nt0 + ni) * 8 + 2 * t;
        *(float2*)&Cs[(wm + g) * 56 + col0]     = make_float2(acc[ni][0], acc[ni][1]);
        *(float2*)&Cs[(wm + g + 8) * 56 + col0] = make_float2(acc[ni][2], acc[ni][3]);
    }
    __syncthreads();

    for (int idx = tid; idx < K1; idx += 256) {
        const int hw = idx / 49, ij = idx - hw * 49;
        const int h = hw / 7,  w = hw - h * 7;
        const int m00 = h * 8 + w;
        const float v = w00 * Cs[m00 * 56 + ij]
                      + w01 * Cs[(m00 + 1) * 56 + ij]
                      + w10 * Cs[(m00 + 8) * 56 + ij]
                      + w11 * Cs[(m00 + 9) * 56 + ij];
        vrow[idx] = __float2half_rn(v);
    }
}

// ---------------- fp16 GEMM1: [12288 x 2432] x W1h^T -> gelu -> h ----------
// 128x128 tile, 128 threads (4 warps of 64x64), 3-stage cp.async, k32 chunks.
// smem rows: 32 halves + pad -> 20 words (conflict-free: g*20+t distinct mod 32)
#define HAW 20                      // words per smem row
#define HSTG (128 * HAW)            // 2560 words per tile stage
#define HGEMM_SMEM (6 * HSTG * 4)   // 61440 B

__global__ __launch_bounds__(128, 2)
void hgemm1(const __half* __restrict__ A,    // [12288][VSTRH]
            const __half* __restrict__ Bt,   // [384][VSTRH]
            const float* __restrict__ bias,
            float* __restrict__ C)           // [12288][384]
{
    extern __shared__ float smg[];
    float* AsBase = smg;                 // 3 x HSTG
    float* BsBase = smg + 3 * HSTG;      // 3 x HSTG

    const int tid  = threadIdx.x;
    const int lane = tid & 31;
    const int warp = tid >> 5;           // 0..3
    const int m0 = blockIdx.y * 128, n0 = blockIdx.x * 128;
    const int wm = (warp >> 1) * 64, wn = (warp & 1) * 64;
    const int t = lane & 3, g = lane >> 2;

    uint32_t sA[3], sB[3];
    {
        uint32_t a = (uint32_t)__cvta_generic_to_shared(AsBase);
        uint32_t b = (uint32_t)__cvta_generic_to_shared(BsBase);
        #pragma unroll
        for (int st = 0; st < 3; st++) {
            sA[st] = a + (st * HSTG + tid * HAW) * 4;
            sB[st] = b + (st * HSTG + tid * HAW) * 4;
        }
    }
    const __half* gA = A  + (size_t)(m0 + tid) * VSTRH;
    const __half* gB = Bt + (size_t)(n0 + tid) * VSTRH;

    const int NIT = VSTRH / 32;   // 76

    auto prefetch = [&](int it, int st) {
        const int k0 = it * 32;
        #pragma unroll
        for (int q = 0; q < 4; q++) {
            cpa16(sA[st] + q * 16, gA + k0 + q * 8, true);
            cpa16(sB[st] + q * 16, gB + k0 + q * 8, true);
        }
        cpa_commit();
    };

    float acc[4][8][4];
    #pragma unroll
    for (int mi = 0; mi < 4; mi++)
        #pragma unroll
        for (int ni = 0; ni < 8; ni++)
            #pragma unroll
            for (int q = 0; q < 4; q++) acc[mi][ni][q] = 0.f;

    prefetch(0, 0);
    if (1 < NIT) prefetch(1, 1);

    for (int it = 0; it < NIT; it++) {
        const int st = it % 3;
        if (it + 2 < NIT) {
            prefetch(it + 2, (it + 2) % 3);
            cpa_wait2();
        } else if (it + 1 < NIT) {
            cpa_wait1();
        } else {
            cpa_wait0();
        }
        __syncthreads();

        const uint32_t* Ab = (const uint32_t*)(AsBase + st * HSTG);
        const uint32_t* Bb = (const uint32_t*)(BsBase + st * HSTG);
        #pragma unroll
        for (int ks = 0; ks < 2; ks++) {
            uint32_t af[4][4], bf[8][2];
            #pragma unroll
            for (int mi = 0; mi < 4; mi++) {
                const int r0 = (wm + mi * 16 + g) * HAW + ks * 8 + t;
                const int r1 = (wm + mi * 16 + g + 8) * HAW + ks * 8 + t;
                af[mi][0] = Ab[r0];
                af[mi][1] = Ab[r1];
                af[mi][2] = Ab[r0 + 4];
                af[mi][3] = Ab[r1 + 4];
            }
            #pragma unroll
            for (int ni = 0; ni < 8; ni++) {
                const int rn = (wn + ni * 8 + g) * HAW + ks * 8 + t;
                bf[ni][0] = Bb[rn];
                bf[ni][1] = Bb[rn + 4];
            }
            #pragma unroll
            for (int mi = 0; mi < 4; mi++)
                #pragma unroll
                for (int ni = 0; ni < 8; ni++)
                    mma_f16(acc[mi][ni], af[mi], bf[ni]);
        }
        __syncthreads();
    }

    // epilogue: bias + gelu + tf32 round (for the tf32 GEMM2), write C
    #pragma unroll
    for (int mi = 0; mi < 4; mi++) {
        const int r0 = m0 + wm + mi * 16 + g;
        #pragma unroll
        for (int ni = 0; ni < 8; ni++) {
            const int c0 = n0 + wn + ni * 8 + 2 * t;
            if (c0 >= 384) continue;
            const float bb0 = bias[c0], bb1 = bias[c0 + 1];
            float v0 = tf32r(gelu_exact(acc[mi][ni][0] + bb0));
            float v1 = tf32r(gelu_exact(acc[mi][ni][1] + bb1));
            float v2 = tf32r(gelu_exact(acc[mi][ni][2] + bb0));
            float v3 = tf32r(gelu_exact(acc[mi][ni][3] + bb1));
            *(float2*)(C + (size_t)r0 * 384 + c0)       = make_float2(v0, v1);
            *(float2*)(C + (size_t)(r0 + 8) * 384 + c0) = make_float2(v2, v3);
        }
    }
}

// ---------------- 3-stage tf32 GEMM (GEMM2), 128 thr, 64x64 warps -----------
#define AST 20
#define BST 136
#define STG_A (128 * AST)
#define STG_B (16 * BST)
#define GEMM_SMEM (3 * (STG_A + STG_B) * 4)

template <bool GELU, bool ROUND_OUT>
__global__ __launch_bounds__(128, 2)
void tf32_gemm_pipe(const float* __restrict__ A, int lda,
                    const float* __restrict__ B, int ldb,
                    const float* __restrict__ bias,
                    float* __restrict__ C, int ldc,
                    int K, int Kvalid)
{
    extern __shared__ float smg[];
    float* AsBase = smg;
    float* BsBase = smg + 3 * STG_A;

    const int tid  = threadIdx.x;
    const int lane = tid & 31;
    const int warp = tid >> 5;
    const int m0 = blockIdx.y * 128, n0 = blockIdx.x * 128;
    const int wm = (warp >> 1) * 64, wn = (warp & 1) * 64;
    const int t = lane & 3, g = lane >> 2;

    const int am  = tid;
    const int bk0 = tid >> 5;
    const int bnc = (tid & 31) * 4;

    uint32_t sA[3], sB[3];
    {
        uint32_t a = (uint32_t)__cvta_generic_to_shared(AsBase);
        uint32_t b = (uint32_t)__cvta_generic_to_shared(BsBase);
        #pragma unroll
        for (int st = 0; st < 3; st++) {
            sA[st] = a + (st * STG_A + am * AST) * 4;
            sB[st] = b + (st * STG_B + bk0 * BST + bnc) * 4;
        }
    }
    const float* gA = A + (size_t)(m0 + am) * lda;
    const float* gB = B + (size_t)bk0 * ldb + n0 + bnc;

    const int NIT = K / 16;

    auto prefetch = [&](int it, int st) {
        const int k0 = it * 16;
        #pragma unroll
        for (int q = 0; q < 4; q++)
            cpa16(sA[st] + q * 16, gA + k0 + q * 4, true);
        #pragma unroll
        for (int q = 0; q < 4; q++)
            cpa16(sB[st] + q * 4 * BST * 4,
                  gB + (size_t)(k0 + q * 4) * ldb,
                  k0 + bk0 + q * 4 < Kvalid);
        cpa_commit();
    };

    float acc[4][8][4];
    #pragma unroll
    for (int mi = 0; mi < 4; mi++)
        #pragma unroll
        for (int ni = 0; ni < 8; ni++)
            #pragma unroll
            for (int q = 0; q < 4; q++) acc[mi][ni][q] = 0.f;

    prefetch(0, 0);
    if (1 < NIT) prefetch(1, 1);

    for (int it = 0; it < NIT; it++) {
        const int st = it % 3;
        if (it + 2 < NIT) {
            prefetch(it + 2, (it + 2) % 3);
            cpa_wait2();
        } else if (it + 1 < NIT) {
            cpa_wait1();
        } else {
            cpa_wait0();
        }
        __syncthreads();

        const float* Ab = AsBase + st * STG_A;
        const float* Bb = BsBase + st * STG_B;
        #pragma unroll
        for (int kb = 0; kb < 16; kb += 8) {
            uint32_t af[4][4], bf[8][2];
            #pragma unroll
            for (int mi = 0; mi < 4; mi++) {
                const int r = (wm + mi * 16 + g) * AST + kb + t;
                af[mi][0] = __float_as_uint(Ab[r]);
                af[mi][1] = __float_as_uint(Ab[r + 8 * AST]);
                af[mi][2] = __float_as_uint(Ab[r + 4]);
                af[mi][3] = __float_as_uint(Ab[r + 8 * AST + 4]);
            }
            #pragma unroll
            for (int ni = 0; ni < 8; ni++) {
                const int cidx = (kb + t) * BST + wn + ni * 8 + g;
                bf[ni][0] = __float_as_uint(Bb[cidx]);
                bf[ni][1] = __float_as_uint(Bb[cidx + 4 * BST]);
            }
            #pragma unroll
            for (int mi = 0; mi < 4; mi++)
                #pragma unroll
                for (int ni = 0; ni < 8; ni++)
                    mma_tf32(acc[mi][ni], af[mi], bf[ni]);
        }
        __syncthreads();
    }

    #pragma unroll
    for (int mi = 0; mi < 4; mi++) {
        const int r0 = m0 + wm + mi * 16 + g;
        #pragma unroll
        for (int ni = 0; ni < 8; ni++) {
            const int c0 = n0 + wn + ni * 8 + 2 * t;
            const float bb0 = bias[c0], bb1 = bias[c0 + 1];
            float v0 = acc[mi][ni][0] + bb0;
            float v1 = acc[mi][ni][1] + bb1;
            float v2 = acc[mi][ni][2] + bb0;
            float v3 = acc[mi][ni][3] + bb1;
            if (GELU) {
                v0 = gelu_exact(v0); v1 = gelu_exact(v1);
                v2 = gelu_exact(v2); v3 = gelu_exact(v3);
            }
            if (ROUND_OUT) {
                v0 = tf32r(v0); v1 = tf32r(v1);
                v2 = tf32r(v2); v3 = tf32r(v3);
            }
            *(float2*)(C + (size_t)r0 * ldc + c0)       = make_float2(v0, v1);
            *(float2*)(C + (size_t)(r0 + 8) * ldc + c0) = make_float2(v2, v3);
        }
    }
}

// ---------------- final assembly: concat + posenc + time embedding ----------------
__global__ void assemble_kernel(const float* __restrict__ emb,
                                const float* __restrict__ coords,
                                const float* __restrict__ vis,
                                const float* __restrict__ conf,
                                float* __restrict__ out)
{
    const int n = blockIdx.x, s = blockIdx.y;
    const int sn = s * N_ + n;

    float rfx = 0.f, rfy = 0.f, rbx = 0.f, rby = 0.f;
    const float cx = coords[sn * 2], cy = coords[sn * 2 + 1];
    if (s < S_ - 1) {
        rfx = cx - coords[((s + 1) * N_ + n) * 2];
        rfy = cy - coords[((s + 1) * N_ + n) * 2 + 1];
    }
    if (s > 0) {
        rbx = cx - coords[((s - 1) * N_ + n) * 2];
        rby = cy - coords[((s - 1) * N_ + n) * 2 + 1];
    }
    float p4[4];
    p4[0] = rfx / 64.f;
    p4[1] = rfy / 48.f;
    p4[2] = rbx / 64.f;
    p4[3] = rby / 48.f;

    float* orow = out + (size_t)(n * S_ + s) * 854;
    for (int f = threadIdx.x; f < 854; f += 256) {
        float v;
        if (f == 0)      v = vis[sn];
        else if (f == 1) v = conf[sn];
        else if (f < 770) {
            const int lev = (f - 2) >> 8;
            const int c   = (f - 2) & 255;
            v = emb[((size_t)(lev * 4096 + sn)) * 256 + c];
        } else {
            const int j = f - 770;
            if (j < 4) v = p4[j];
            else if (j < 44) {
                const int i = (j - 4) >> 2, q = (j - 4) & 3;
                v = sinf(exp2f((float)i) * p4[q]);
            } else {
                const int i = (j - 44) >> 2, q = (j - 44) & 3;
                v = sinf(exp2f((float)i) * p4[q] + 1.5707963267948966f);
            }
        }
        const int i2 = (f < 427) ? f : f - 427;
        const float omega = expf(-9.210340371976184f * (float)i2 / 427.0f);
        const float ang = (float)s * omega;
        v += (f < 427) ? sinf(ang) : cosf(ang);
        orow[f] = v;
    }
}

// ---------------- launch ----------------
extern "C" void kernel_launch(void* const* d_in, const int* in_sizes, int n_in,
                              void* d_out, int out_size)
{
    (void)in_sizes; (void)n_in; (void)out_size;
    const float* fm0    = (const float*)d_in[0];
    const float* fm1    = (const float*)d_in[1];
    const float* fm2    = (const float*)d_in[2];
    const float* coords = (const float*)d_in[3];
    const float* tf0    = (const float*)d_in[4];
    const float* tf1    = (const float*)d_in[5];
    const float* tf2    = (const float*)d_in[6];
    const float* vis    = (const float*)d_in[7];
    const float* conf   = (const float*)d_in[8];
    const float* W1     = (const float*)d_in[9];
    const float* b1     = (const float*)d_in[10];
    const float* W2     = (const float*)d_in[11];
    const float* W2b    = (const float*)d_in[12];
    float* out = (float*)d_out;

    float *fT, *hbuf, *ebuf, *w2r;
    __half *volh, *w1h;
    cudaGetSymbolAddress((void**)&fT,   g_fmapT);
    cudaGetSymbolAddress((void**)&volh, g_volh);
    cudaGetSymbolAddress((void**)&hbuf, g_h);
    cudaGetSymbolAddress((void**)&ebuf, g_emb);
    cudaGetSymbolAddress((void**)&w1h,  g_w1h);
    cudaGetSymbolAddress((void**)&w2r,  g_w2r);

    cudaFuncSetAttribute(vol_kernel, cudaFuncAttributeMaxDynamicSharedMemorySize, VOL_SMEM);
    cudaFuncSetAttribute(hgemm1,     cudaFuncAttributeMaxDynamicSharedMemorySize, HGEMM_SMEM);
    cudaFuncSetAttribute(tf32_gemm_pipe<false, false>, cudaFuncAttributeMaxDynamicSharedMemorySize, GEMM_SMEM);

    // launch order keeps gemm1 at profiled slot #4
    transpose_all_kernel<<<dim3(126, 4, 16), dim3(32, 8)>>>(fm0, fm1, fm2, fT);

    const int NP = 384 * VSTRH + 384 * 256;
    pack_kernel<<<(NP + 255) / 256, 256>>>(W1, w1h, W2, w2r);

    vol_kernel<<<dim3(N_, S_, 3), 256, VOL_SMEM>>>(fT, tf0, tf1, tf2, coords, volh);

    hgemm1<<<dim3(3, 96), 128, HGEMM_SMEM>>>(volh, w1h, b1, hbuf);

    tf32_gemm_pipe<false, false><<<dim3(2, 96), 128, GEMM_SMEM>>>(hbuf, 384, w2r, 256, W2b, ebuf, 256, 384, 384);

    assemble_kernel<<<dim3(N_, S_), 256>>>(ebuf, coords, vis, conf, out);
}